// round 1
// baseline (speedup 1.0000x reference)
#include <cuda_runtime.h>
#include <math.h>

#define NUM_USERS 8192
#define ROW 1000
#define TOP_K 10
#define THREADS 256

__global__ __launch_bounds__(THREADS)
void metric_kernel(const float* __restrict__ logits,
                   const int*   __restrict__ dup,
                   float* __restrict__ out) {
    const int user = blockIdx.x;
    const long base = (long)user * ROW;

    // logits layout: [N*ROW, 1, 2] -> element [i,0,1] is ((const float2*)logits)[i].y
    const float2* __restrict__ lg = (const float2*)logits;

    const float BIG_NEG = -3.402823466e38f;  // finfo(float32).min

    // masked logit of element 0 (broadcast L1 hit for all threads)
    const int   d0 = dup[base];
    const float l0 = (d0 != 0) ? BIG_NEG : lg[base].y;

    int cnt  = 0;   // # elements strictly greater than masked[0]
    int dsum = 0;   // sum of dup mask over the row

    #pragma unroll 4
    for (int j = threadIdx.x; j < ROW; j += THREADS) {
        int   d = dup[base + j];
        float v = (d != 0) ? BIG_NEG : lg[base + j].y;
        cnt  += (v > l0) ? 1 : 0;
        dsum += d;
    }

    // warp reduction
    #pragma unroll
    for (int o = 16; o > 0; o >>= 1) {
        cnt  += __shfl_down_sync(0xFFFFFFFFu, cnt,  o);
        dsum += __shfl_down_sync(0xFFFFFFFFu, dsum, o);
    }

    __shared__ int sc[THREADS / 32];
    __shared__ int sd[THREADS / 32];
    const int wid = threadIdx.x >> 5;
    if ((threadIdx.x & 31) == 0) { sc[wid] = cnt; sd[wid] = dsum; }
    __syncthreads();

    if (threadIdx.x == 0) {
        int c = 0, d = 0;
        #pragma unroll
        for (int i = 0; i < THREADS / 32; i++) { c += sc[i]; d += sd[i]; }

        float pos    = (float)c;
        float intop  = (pos < (float)TOP_K) ? 1.0f : 0.0f;
        float ndcg   = intop * (0.6931471805599453f / logf(pos + 2.0f));
        float weight = (d != (ROW - 1)) ? 1.0f : 0.0f;

        out[user]                 = intop;
        out[NUM_USERS + user]     = ndcg;
        out[2 * NUM_USERS + user] = weight;
    }
}

extern "C" void kernel_launch(void* const* d_in, const int* in_sizes, int n_in,
                              void* d_out, int out_size) {
    const float* logits = (const float*)d_in[0];
    const int*   dup    = (const int*)d_in[1];
    float*       out    = (float*)d_out;

    metric_kernel<<<NUM_USERS, THREADS>>>(logits, dup, out);
}

// round 2
// speedup vs baseline: 1.5203x; 1.5203x over previous
#include <cuda_runtime.h>
#include <math.h>

#define NUM_USERS 8192
#define ROW 1000
#define TOP_K 10
#define THREADS 256
#define ACTIVE 250   // 250 threads x 4 elements = 1000 = ROW

__global__ __launch_bounds__(THREADS)
void metric_kernel(const float4* __restrict__ lg4,   // logits as float4: 2 (pair) elems each
                   const int4*   __restrict__ dup4,  // dup as int4: 4 elems each
                   float* __restrict__ out) {
    const int user = blockIdx.x;
    const int t = threadIdx.x;

    const long f4base = (long)user * (ROW / 2);   // 500 float4 per row
    const long i4base = (long)user * (ROW / 4);   // 250 int4 per row

    const float BIG_NEG = -3.402823466e38f;  // finfo(float32).min

    int cnt  = 0;
    int dsum = 0;

    if (t < ACTIVE) {
        // Issue all loads up front (independent -> MLP 4)
        const int4   d  = __ldcs(&dup4[i4base + t]);
        const float4 a  = __ldcs(&lg4[f4base + 2 * t]);
        const float4 b  = __ldcs(&lg4[f4base + 2 * t + 1]);
        // broadcast loads for element 0 (L1/L2 hit after first warp)
        const int    d0raw = __ldg(&((const int*)dup4)[i4base * 4]);
        const float  l0raw = __ldg(&((const float*)lg4)[f4base * 4 + 1]);

        const float l0 = (d0raw != 0) ? BIG_NEG : l0raw;

        const float v0 = (d.x != 0) ? BIG_NEG : a.y;
        const float v1 = (d.y != 0) ? BIG_NEG : a.w;
        const float v2 = (d.z != 0) ? BIG_NEG : b.y;
        const float v3 = (d.w != 0) ? BIG_NEG : b.w;

        cnt  = (v0 > l0) + (v1 > l0) + (v2 > l0) + (v3 > l0);
        dsum = d.x + d.y + d.z + d.w;
    }

    // warp reduction
    #pragma unroll
    for (int o = 16; o > 0; o >>= 1) {
        cnt  += __shfl_down_sync(0xFFFFFFFFu, cnt,  o);
        dsum += __shfl_down_sync(0xFFFFFFFFu, dsum, o);
    }

    __shared__ int sc[THREADS / 32];
    __shared__ int sd[THREADS / 32];
    const int wid = t >> 5;
    if ((t & 31) == 0) { sc[wid] = cnt; sd[wid] = dsum; }
    __syncthreads();

    if (t == 0) {
        int c = 0, d = 0;
        #pragma unroll
        for (int i = 0; i < THREADS / 32; i++) { c += sc[i]; d += sd[i]; }

        float pos    = (float)c;
        float intop  = (pos < (float)TOP_K) ? 1.0f : 0.0f;
        float ndcg   = intop * (0.6931471805599453f / logf(pos + 2.0f));
        float weight = (d != (ROW - 1)) ? 1.0f : 0.0f;

        out[user]                 = intop;
        out[NUM_USERS + user]     = ndcg;
        out[2 * NUM_USERS + user] = weight;
    }
}

extern "C" void kernel_launch(void* const* d_in, const int* in_sizes, int n_in,
                              void* d_out, int out_size) {
    const float4* lg4  = (const float4*)d_in[0];
    const int4*   dup4 = (const int4*)d_in[1];
    float*        out  = (float*)d_out;

    metric_kernel<<<NUM_USERS, THREADS>>>(lg4, dup4, out);
}